// round 7
// baseline (speedup 1.0000x reference)
#include <cuda_runtime.h>
#include <cuda_bf16.h>

// NDFT type-2 with conjugate-pair symmetry over k1 (f_hat is real):
//   y[b,m] = sum_{k1,k2=-32..31} f[k1,k2] exp(-2pi*i(k1x1+k2x2))
// Pair rows +-t:  f[t]e^{-i p} + f[-t]e^{+i p} = fs*cos(p) - i*fd*sin(p),
//   fs = f[t]+f[-t], fd = f[t]-f[-t]  (t=0: fd=0; t=32 carries k1=-32: fs=f, fd=-f)
// Per k2 column: P[c] += fs*cos, Q[c] += sin*fd  (REAL packed accumulation),
// then y = sum_a C_a * sum_c E2f[c]*(P[c] - i Q[c]),  (k2 = 16a + c - 32).
//
// Block: 256 thr = 8 warps; warp w: a = w&3 (k2 radix digit), h = w>>2
// (t-range half). Lane = sample point (32/block). fs/fd precomputed in smem;
// all hot-loop shared loads are 32-lane broadcasts.

#define B_DIM 2
#define M_DIM 8192
#define N1 64
#define N2 64
#define K_TOT (N1 * N2)
#define TPB 256
#define NWARP 8
#define PTS 32
#define BLOCKS_PER_B (M_DIM / PTS)           // 256
#define TROWS 33                             // t = 0..32

typedef unsigned long long ull;

#define PACK2(d, lo, hi) \
    asm("mov.b64 %0, {%1, %2};" : "=l"(d) \
        : "r"(__float_as_uint(lo)), "r"(__float_as_uint(hi)))
#define FMA2(d, a, b, c) \
    asm("fma.rn.f32x2 %0, %1, %2, %3;" : "=l"(d) : "l"(a), "l"(b), "l"(c))
#define UNPACK2(lo, hi, s) do { unsigned int _l, _h; \
    asm("mov.b64 {%0, %1}, %2;" : "=r"(_l), "=r"(_h) : "l"(s)); \
    (lo) = __uint_as_float(_l); (hi) = __uint_as_float(_h); } while (0)

__global__ __launch_bounds__(TPB, 4) void ndft_kernel(
    const float* __restrict__ x,      // [B, M, 2]
    const float* __restrict__ f_hat,  // [B, 64, 64]
    float* __restrict__ out,
    const int real_only)
{
    __shared__ __align__(16) float sfs[TROWS * N2];   // fs rows t=0..32
    __shared__ __align__(16) float sfd[TROWS * N2];   // fd rows t=0..32
    __shared__ float2 sy[NWARP][PTS];

    const int b    = blockIdx.x / BLOCKS_PER_B;
    const int mblk = blockIdx.x % BLOCKS_PER_B;
    const int tid  = threadIdx.x;
    const int w    = tid >> 5;
    const int lane = tid & 31;
    const int a    = w & 3;                  // k2 radix digit
    const int h    = w >> 2;                 // t-range half
    const int m    = mblk * PTS + lane;

    // ---- build fs/fd in shared (f rows: storage row r = k1 + 32) ----
    {
        const float* fb = f_hat + b * K_TOT;
        for (int idx = tid; idx < TROWS * N2; idx += TPB) {
            const int t = idx >> 6;          // 0..32
            const int c = idx & 63;
            float s, d;
            if (t == 0) {                    // k1 = 0
                s = fb[32 * N2 + c];
                d = 0.0f;
            } else if (t == 32) {            // k1 = -32 (unpaired)
                const float v = fb[c];
                s = v;
                d = -v;
            } else {                         // pair (+t, -t)
                const float fp = fb[(32 + t) * N2 + c];
                const float fm = fb[(32 - t) * N2 + c];
                s = fp + fm;
                d = fp - fm;
            }
            sfs[idx] = s;
            sfd[idx] = d;
        }
    }
    __syncthreads();

    const float2 xv = reinterpret_cast<const float2*>(x)[b * M_DIM + m];
    const float x1 = xv.x, x2 = xv.y;

    // ---- twiddles (sincospif: arg in units of pi) ----
    float rc, rs;                      // rotation by +2*pi*x1 per t step
    sincospif(2.0f * x1, &rs, &rc);
    const int t0 = h ? 17 : 0;
    const int t1 = h ? 33 : 17;
    float ct, st;                      // (cos, sin)(2*pi*t0*x1), anchored
    sincospif(2.0f * (float)t0 * x1, &st, &ct);
    float w2r, w2i;                    // w2 = exp(-2*pi*i*x2) for E2f tail
    sincospif(-2.0f * x2, &w2i, &w2r);
    float Cr, Ci;                      // C_a = exp(-2*pi*i*(16a-32)*x2)
    sincospif((64.0f - 32.0f * (float)a) * x2, &Ci, &Cr);

    // packed REAL accumulators over local c in [0,16)
    ull P[8], Q[8];
    #pragma unroll
    for (int p = 0; p < 8; ++p) { P[p] = 0ull; Q[p] = 0ull; }

    const ulonglong2* fsv =
        reinterpret_cast<const ulonglong2*>(sfs + t0 * N2 + a * 16);
    const ulonglong2* fdv =
        reinterpret_cast<const ulonglong2*>(sfd + t0 * N2 + a * 16);

    #pragma unroll 4
    for (int t = t0; t < t1; ++t) {
        ull crr, sii;
        PACK2(crr, ct, ct);
        PACK2(sii, st, st);

        const ulonglong2 s0 = fsv[0];   // broadcast LDS.128 (c = 0..3)
        const ulonglong2 s1 = fsv[1];
        const ulonglong2 s2 = fsv[2];
        const ulonglong2 s3 = fsv[3];
        const ulonglong2 d0 = fdv[0];
        const ulonglong2 d1 = fdv[1];
        const ulonglong2 d2 = fdv[2];
        const ulonglong2 d3 = fdv[3];

        FMA2(P[0], s0.x, crr, P[0]);
        FMA2(P[1], s0.y, crr, P[1]);
        FMA2(P[2], s1.x, crr, P[2]);
        FMA2(P[3], s1.y, crr, P[3]);
        FMA2(P[4], s2.x, crr, P[4]);
        FMA2(P[5], s2.y, crr, P[5]);
        FMA2(P[6], s3.x, crr, P[6]);
        FMA2(P[7], s3.y, crr, P[7]);
        FMA2(Q[0], d0.x, sii, Q[0]);
        FMA2(Q[1], d0.y, sii, Q[1]);
        FMA2(Q[2], d1.x, sii, Q[2]);
        FMA2(Q[3], d1.y, sii, Q[3]);
        FMA2(Q[4], d2.x, sii, Q[4]);
        FMA2(Q[5], d2.y, sii, Q[5]);
        FMA2(Q[6], d3.x, sii, Q[6]);
        FMA2(Q[7], d3.y, sii, Q[7]);

        // rotate (ct, st) by +2*pi*x1 (short anchored chain, <= 17 steps)
        const float nc = ct * rc - st * rs;
        st = ct * rs + st * rc;
        ct = nc;

        fsv += N2 / 4;
        fdv += N2 / 4;
    }

    // ---- tail: T = sum_c E2f[c] * (P[c] - i Q[c]);  y_w = C_a * T ----
    float Tr = 0.0f, Ti = 0.0f;
    {
        float fr = 1.0f, fi = 0.0f;    // E2f[c] = w2^c
        #pragma unroll
        for (int p = 0; p < 8; ++p) {
            float p0, p1, q0, q1;
            UNPACK2(p0, p1, P[p]);
            UNPACK2(q0, q1, Q[p]);
            // c = 2p: (fr + i fi)(p0 - i q0)
            Tr += fr * p0 + fi * q0;
            Ti += fi * p0 - fr * q0;
            float tt = fr * w2r - fi * w2i;
            fi = fr * w2i + fi * w2r;
            fr = tt;
            // c = 2p+1
            Tr += fr * p1 + fi * q1;
            Ti += fi * p1 - fr * q1;
            tt = fr * w2r - fi * w2i;
            fi = fr * w2i + fi * w2r;
            fr = tt;
        }
    }
    const float yr = Cr * Tr - Ci * Ti;
    const float yi = Cr * Ti + Ci * Tr;

    // ---- cross-warp reduction (8 partials per point) ----
    sy[w][lane] = make_float2(yr, yi);
    __syncthreads();

    if (tid < PTS) {
        float2 acc = sy[0][tid];
        #pragma unroll
        for (int ww = 1; ww < NWARP; ++ww) {
            acc.x += sy[ww][tid].x;
            acc.y += sy[ww][tid].y;
        }
        const int mo = mblk * PTS + tid;
        if (real_only) {
            out[b * M_DIM + mo] = acc.x;
        } else {
            reinterpret_cast<float2*>(out)[b * M_DIM + mo] = acc;
        }
    }
}

extern "C" void kernel_launch(void* const* d_in, const int* in_sizes, int n_in,
                              void* d_out, int out_size) {
    // Select inputs by element count (metadata order may differ):
    //   x: 2*8192*2 = 32768, f_hat: 2*64*64 = 8192
    const float* x;
    const float* f_hat;
    if (in_sizes[0] == B_DIM * M_DIM * 2) {
        x = (const float*)d_in[0];
        f_hat = (const float*)d_in[1];
    } else {
        x = (const float*)d_in[1];
        f_hat = (const float*)d_in[0];
    }

    float* out = (float*)d_out;
    const int real_only = (out_size == B_DIM * M_DIM) ? 1 : 0;

    ndft_kernel<<<B_DIM * BLOCKS_PER_B, TPB>>>(x, f_hat, out, real_only);
}

// round 9
// speedup vs baseline: 1.1758x; 1.1758x over previous
#include <cuda_runtime.h>
#include <cuda_bf16.h>

// NDFT type-2 with conjugate-pair symmetry over k1 (f_hat real):
//   pair rows +-t: f[t]e^{-ip} + f[-t]e^{+ip} = fs*cos(p) - i*fd*sin(p)
//   fs = f[t]+f[-t], fd = f[t]-f[-t]
//   t=0  (k1=0, single row): fs=f, fd arbitrary since sin(0)=0 exactly
//   t=32 (k1=-32, unpaired): fs=f, fd=-f
// Radix on k2: k2 = 16a + c - 32. Per warp (a, t-third):
//   acc[c] = (P_c, Q_c) packed; ONE fma.rn.f32x2 per c per row:
//   (P,Q) += (fs_c, fd_c) * (cos_t, sin_t).
// Tail: T = sum_c w2^c (P_c - i Q_c); y_w = C_a * T; smem reduce over 12 warps.
//
// smem layout: fsd[t][a][c] as interleaved pairs (fs,fd):
//   float index = t*128 + a*32 + c*2.

#define B_DIM 2
#define M_DIM 8192
#define N1 64
#define N2 64
#define K_TOT (N1 * N2)
#define TPB 384
#define NWARP 12
#define PTS 32
#define BLOCKS_PER_B (M_DIM / PTS)           // 256
#define TROWS 33                             // t = 0..32

typedef unsigned long long ull;

#define PACK2(d, lo, hi) \
    asm("mov.b64 %0, {%1, %2};" : "=l"(d) \
        : "r"(__float_as_uint(lo)), "r"(__float_as_uint(hi)))
#define FMA2(d, a, b, c) \
    asm("fma.rn.f32x2 %0, %1, %2, %3;" : "=l"(d) : "l"(a), "l"(b), "l"(c))
#define UNPACK2(lo, hi, s) do { unsigned int _l, _h; \
    asm("mov.b64 {%0, %1}, %2;" : "=r"(_l), "=r"(_h) : "l"(s)); \
    (lo) = __uint_as_float(_l); (hi) = __uint_as_float(_h); } while (0)

__global__ __launch_bounds__(TPB) void ndft_kernel(
    const float* __restrict__ x,      // [B, M, 2]
    const float* __restrict__ f_hat,  // [B, 64, 64]
    float* __restrict__ out,
    const int real_only)
{
    __shared__ __align__(16) float sfd[TROWS * 128];  // (fs,fd) interleaved
    __shared__ float2 sy[NWARP][PTS];

    const int b    = blockIdx.x / BLOCKS_PER_B;
    const int mblk = blockIdx.x % BLOCKS_PER_B;
    const int tid  = threadIdx.x;
    const int w    = tid >> 5;
    const int lane = tid & 31;
    const int a    = w & 3;                  // k2 radix digit
    const int seg  = w >> 2;                 // t-third: rows 11*seg .. +11
    const int m    = mblk * PTS + lane;

    // ---- build fs/fd interleaved, vectorized & coalesced ----
    // t in {0, 32}: fp = 0 (t=0: single row, fd killed by sin(0)=0;
    //               t=32: unpaired k1=-32 row -> fs=f, fd=-f).
    {
        const float* fb = f_hat + b * K_TOT;
        for (int idx = tid; idx < TROWS * 16; idx += TPB) {
            const int t = idx >> 4;
            const int g = idx & 15;
            float4 fp;
            if (t >= 1 && t <= 31)
                fp = *reinterpret_cast<const float4*>(fb + (32 + t) * N2 + g * 4);
            else
                fp = make_float4(0.f, 0.f, 0.f, 0.f);
            const float4 fm = *reinterpret_cast<const float4*>(fb + (32 - t) * N2 + g * 4);
            float4* dst = reinterpret_cast<float4*>(sfd + t * 128 + g * 8);
            dst[0] = make_float4(fp.x + fm.x, fp.x - fm.x, fp.y + fm.y, fp.y - fm.y);
            dst[1] = make_float4(fp.z + fm.z, fp.z - fm.z, fp.w + fm.w, fp.w - fm.w);
        }
    }
    __syncthreads();

    const float2 xv = reinterpret_cast<const float2*>(x)[b * M_DIM + m];
    const float x1 = xv.x, x2 = xv.y;

    // ---- twiddles (sincospif: arg in units of pi) ----
    float rc, rs;                      // rotation by +2*pi*x1 per t step
    sincospif(2.0f * x1, &rs, &rc);
    const int t0 = seg * 11;           // 0, 11, 22 (11 rows each; 33 total)
    float ct, st;                      // cis(2*pi*t0*x1), anchored exactly
    sincospif(2.0f * (float)t0 * x1, &st, &ct);
    float w2r, w2i;                    // w2 = exp(-2*pi*i*x2)
    sincospif(-2.0f * x2, &w2i, &w2r);
    float Cr, Ci;                      // C_a = exp(-2*pi*i*(16a-32)*x2)
    sincospif((64.0f - 32.0f * (float)a) * x2, &Ci, &Cr);

    // packed accumulators: acc[c] = (P_c, Q_c)
    ull acc[16];
    #pragma unroll
    for (int c = 0; c < 16; ++c) acc[c] = 0ull;

    const ulonglong2* fsd =
        reinterpret_cast<const ulonglong2*>(sfd + t0 * 128 + a * 32);

    #pragma unroll
    for (int t = 0; t < 11; ++t) {
        ull cs;
        PACK2(cs, ct, st);             // (cos_t, sin_t)

        // 8 broadcast LDS.128: pairs (fs,fd) for c = 0..15
        const ulonglong2 v0 = fsd[0];
        const ulonglong2 v1 = fsd[1];
        const ulonglong2 v2 = fsd[2];
        const ulonglong2 v3 = fsd[3];
        const ulonglong2 v4 = fsd[4];
        const ulonglong2 v5 = fsd[5];
        const ulonglong2 v6 = fsd[6];
        const ulonglong2 v7 = fsd[7];

        FMA2(acc[0],  v0.x, cs, acc[0]);
        FMA2(acc[1],  v0.y, cs, acc[1]);
        FMA2(acc[2],  v1.x, cs, acc[2]);
        FMA2(acc[3],  v1.y, cs, acc[3]);
        FMA2(acc[4],  v2.x, cs, acc[4]);
        FMA2(acc[5],  v2.y, cs, acc[5]);
        FMA2(acc[6],  v3.x, cs, acc[6]);
        FMA2(acc[7],  v3.y, cs, acc[7]);
        FMA2(acc[8],  v4.x, cs, acc[8]);
        FMA2(acc[9],  v4.y, cs, acc[9]);
        FMA2(acc[10], v5.x, cs, acc[10]);
        FMA2(acc[11], v5.y, cs, acc[11]);
        FMA2(acc[12], v6.x, cs, acc[12]);
        FMA2(acc[13], v6.y, cs, acc[13]);
        FMA2(acc[14], v7.x, cs, acc[14]);
        FMA2(acc[15], v7.y, cs, acc[15]);

        // rotate cis by +2*pi*x1 (short anchored chain, <= 11 steps)
        const float nc = ct * rc - st * rs;
        st = ct * rs + st * rc;
        ct = nc;

        fsd += 128 / 4;                // next t row (128 floats)
    }

    // ---- tail: T = sum_c w2^c * (P_c - i Q_c);  y_w = C_a * T ----
    float Tr = 0.0f, Ti = 0.0f;
    {
        float fr = 1.0f, fi = 0.0f;
        #pragma unroll
        for (int c = 0; c < 16; ++c) {
            float p, q;
            UNPACK2(p, q, acc[c]);
            Tr += fr * p + fi * q;
            Ti += fi * p - fr * q;
            const float tt = fr * w2r - fi * w2i;
            fi = fr * w2i + fi * w2r;
            fr = tt;
        }
    }
    const float yr = Cr * Tr - Ci * Ti;
    const float yi = Cr * Ti + Ci * Tr;

    // ---- cross-warp reduction (12 partials per point) ----
    sy[w][lane] = make_float2(yr, yi);
    __syncthreads();

    if (tid < PTS) {
        float2 s = sy[0][tid];
        #pragma unroll
        for (int ww = 1; ww < NWARP; ++ww) {
            s.x += sy[ww][tid].x;
            s.y += sy[ww][tid].y;
        }
        const int mo = mblk * PTS + tid;
        if (real_only) {
            out[b * M_DIM + mo] = s.x;
        } else {
            reinterpret_cast<float2*>(out)[b * M_DIM + mo] = s;
        }
    }
}

extern "C" void kernel_launch(void* const* d_in, const int* in_sizes, int n_in,
                              void* d_out, int out_size) {
    // Select inputs by element count (metadata order may differ):
    //   x: 2*8192*2 = 32768, f_hat: 2*64*64 = 8192
    const float* x;
    const float* f_hat;
    if (in_sizes[0] == B_DIM * M_DIM * 2) {
        x = (const float*)d_in[0];
        f_hat = (const float*)d_in[1];
    } else {
        x = (const float*)d_in[1];
        f_hat = (const float*)d_in[0];
    }

    float* out = (float*)d_out;
    const int real_only = (out_size == B_DIM * M_DIM) ? 1 : 0;

    ndft_kernel<<<B_DIM * BLOCKS_PER_B, TPB>>>(x, f_hat, out, real_only);
}

// round 10
// speedup vs baseline: 1.5552x; 1.3227x over previous
#include <cuda_runtime.h>
#include <cuda_bf16.h>

// NDFT type-2 with conjugate-pair symmetry over k1 (f_hat real):
//   pair rows +-t: f[t]e^{-ip} + f[-t]e^{+ip} = fs*cos(p) - i*fd*sin(p)
//   fs = f[t]+f[-t], fd = f[t]-f[-t]
//   t=0  (k1=0): fs=f, fd value irrelevant (sin(0)=0); we set fd=-f
//   t=32 (k1=-32, unpaired): fs=f, fd=-f;  t=33: zero pad row
// Radix on k2: k2 = 16a + c - 32. Warp (a = w&3, t-half h = w>>2):
//   17 t-rows each (h=0: t=0..16, h=1: t=17..33; row 33 contributes 0).
//   acc[c] = (P_c, Q_c) packed; ONE fma.rn.f32x2 per c per row.
// Tail: T = sum_c w2^c (P_c - i Q_c); y_w = C_a * T; smem reduce (8 warps).
// All twiddles via fast MUFU __sincosf (err ~1e-5 << 1e-3 threshold).

#define B_DIM 2
#define M_DIM 8192
#define N1 64
#define N2 64
#define K_TOT (N1 * N2)
#define TPB 256
#define NWARP 8
#define PTS 32
#define BLOCKS_PER_B (M_DIM / PTS)           // 256
#define TROWS 34                             // t = 0..32 + zero pad row 33
#define ROWS_PW 17

#define PI_F     3.14159265358979f
#define TWO_PI_F 6.28318530717959f

typedef unsigned long long ull;

#define PACK2(d, lo, hi) \
    asm("mov.b64 %0, {%1, %2};" : "=l"(d) \
        : "r"(__float_as_uint(lo)), "r"(__float_as_uint(hi)))
#define FMA2(d, a, b, c) \
    asm("fma.rn.f32x2 %0, %1, %2, %3;" : "=l"(d) : "l"(a), "l"(b), "l"(c))
#define UNPACK2(lo, hi, s) do { unsigned int _l, _h; \
    asm("mov.b64 {%0, %1}, %2;" : "=r"(_l), "=r"(_h) : "l"(s)); \
    (lo) = __uint_as_float(_l); (hi) = __uint_as_float(_h); } while (0)

__global__ __launch_bounds__(TPB, 4) void ndft_kernel(
    const float* __restrict__ x,      // [B, M, 2]
    const float* __restrict__ f_hat,  // [B, 64, 64]
    float* __restrict__ out,
    const int real_only)
{
    __shared__ __align__(16) float sfd[TROWS * 128];  // (fs,fd) interleaved
    __shared__ float2 sy[NWARP][PTS];

    const int b    = blockIdx.x / BLOCKS_PER_B;
    const int mblk = blockIdx.x % BLOCKS_PER_B;
    const int tid  = threadIdx.x;
    const int w    = tid >> 5;
    const int lane = tid & 31;
    const int a    = w & 3;                  // k2 radix digit
    const int h    = w >> 2;                 // t-half
    const int m    = mblk * PTS + lane;

    // ---- build fs/fd interleaved: fsd[t*128 + a*32 + c*2] = (fs, fd) ----
    {
        const float* fb = f_hat + b * K_TOT;
        for (int idx = tid; idx < TROWS * 16; idx += TPB) {
            const int t = idx >> 4;
            const int g = idx & 15;
            float4 fp = make_float4(0.f, 0.f, 0.f, 0.f);
            float4 fm = make_float4(0.f, 0.f, 0.f, 0.f);
            if (t >= 1 && t <= 31)
                fp = *reinterpret_cast<const float4*>(fb + (32 + t) * N2 + g * 4);
            if (t <= 32)
                fm = *reinterpret_cast<const float4*>(fb + (32 - t) * N2 + g * 4);
            float4* dst = reinterpret_cast<float4*>(sfd + t * 128 + g * 8);
            dst[0] = make_float4(fp.x + fm.x, fp.x - fm.x, fp.y + fm.y, fp.y - fm.y);
            dst[1] = make_float4(fp.z + fm.z, fp.z - fm.z, fp.w + fm.w, fp.w - fm.w);
        }
    }
    __syncthreads();

    const float2 xv = reinterpret_cast<const float2*>(x)[b * M_DIM + m];
    const float x1 = xv.x, x2 = xv.y;

    // ---- twiddles via MUFU (__sincosf), args in radians ----
    float rc, rs;                      // rotation cis(+2*pi*x1) per t step
    __sincosf(TWO_PI_F * x1, &rs, &rc);
    float ct, st;                      // anchor cis(2*pi*t0*x1), t0 = 17h
    if (h == 0) { ct = 1.0f; st = 0.0f; }
    else        __sincosf(TWO_PI_F * 17.0f * x1, &st, &ct);
    float w2r, w2i;                    // w2 = cis(-2*pi*x2)
    __sincosf(-TWO_PI_F * x2, &w2i, &w2r);
    float Cr, Ci;                      // C_a = cis(-2*pi*(16a-32)*x2)
    __sincosf((64.0f - 32.0f * (float)a) * PI_F * x2, &Ci, &Cr);

    // packed accumulators: acc[c] = (P_c, Q_c)
    ull acc[16];
    #pragma unroll
    for (int c = 0; c < 16; ++c) acc[c] = 0ull;

    const ulonglong2* fsd = reinterpret_cast<const ulonglong2*>(
        sfd + (h * ROWS_PW) * 128 + a * 32);

    #pragma unroll
    for (int t = 0; t < ROWS_PW; ++t) {
        ull cs;
        PACK2(cs, ct, st);             // (cos_t, sin_t)

        // 8 broadcast LDS.128: pairs (fs,fd) for c = 0..15
        const ulonglong2 v0 = fsd[0];
        const ulonglong2 v1 = fsd[1];
        const ulonglong2 v2 = fsd[2];
        const ulonglong2 v3 = fsd[3];
        const ulonglong2 v4 = fsd[4];
        const ulonglong2 v5 = fsd[5];
        const ulonglong2 v6 = fsd[6];
        const ulonglong2 v7 = fsd[7];

        FMA2(acc[0],  v0.x, cs, acc[0]);
        FMA2(acc[1],  v0.y, cs, acc[1]);
        FMA2(acc[2],  v1.x, cs, acc[2]);
        FMA2(acc[3],  v1.y, cs, acc[3]);
        FMA2(acc[4],  v2.x, cs, acc[4]);
        FMA2(acc[5],  v2.y, cs, acc[5]);
        FMA2(acc[6],  v3.x, cs, acc[6]);
        FMA2(acc[7],  v3.y, cs, acc[7]);
        FMA2(acc[8],  v4.x, cs, acc[8]);
        FMA2(acc[9],  v4.y, cs, acc[9]);
        FMA2(acc[10], v5.x, cs, acc[10]);
        FMA2(acc[11], v5.y, cs, acc[11]);
        FMA2(acc[12], v6.x, cs, acc[12]);
        FMA2(acc[13], v6.y, cs, acc[13]);
        FMA2(acc[14], v7.x, cs, acc[14]);
        FMA2(acc[15], v7.y, cs, acc[15]);

        // rotate cis by +2*pi*x1 (<=17-step chain, MUFU-anchored)
        const float nc = ct * rc - st * rs;
        st = ct * rs + st * rc;
        ct = nc;

        fsd += 128 / 4;                // next t row (128 floats)
    }

    // ---- tail: T = sum_c w2^c * (P_c - i Q_c);  y_w = C_a * T ----
    float Tr = 0.0f, Ti = 0.0f;
    {
        float fr = 1.0f, fi = 0.0f;
        #pragma unroll
        for (int c = 0; c < 16; ++c) {
            float p, q;
            UNPACK2(p, q, acc[c]);
            Tr += fr * p + fi * q;
            Ti += fi * p - fr * q;
            const float tt = fr * w2r - fi * w2i;
            fi = fr * w2i + fi * w2r;
            fr = tt;
        }
    }
    const float yr = Cr * Tr - Ci * Ti;
    const float yi = Cr * Ti + Ci * Tr;

    // ---- cross-warp reduction (8 partials per point) ----
    sy[w][lane] = make_float2(yr, yi);
    __syncthreads();

    if (tid < PTS) {
        float2 s = sy[0][tid];
        #pragma unroll
        for (int ww = 1; ww < NWARP; ++ww) {
            s.x += sy[ww][tid].x;
            s.y += sy[ww][tid].y;
        }
        const int mo = mblk * PTS + tid;
        if (real_only) {
            out[b * M_DIM + mo] = s.x;
        } else {
            reinterpret_cast<float2*>(out)[b * M_DIM + mo] = s;
        }
    }
}

extern "C" void kernel_launch(void* const* d_in, const int* in_sizes, int n_in,
                              void* d_out, int out_size) {
    // Select inputs by element count (metadata order may differ):
    //   x: 2*8192*2 = 32768, f_hat: 2*64*64 = 8192
    const float* x;
    const float* f_hat;
    if (in_sizes[0] == B_DIM * M_DIM * 2) {
        x = (const float*)d_in[0];
        f_hat = (const float*)d_in[1];
    } else {
        x = (const float*)d_in[1];
        f_hat = (const float*)d_in[0];
    }

    float* out = (float*)d_out;
    const int real_only = (out_size == B_DIM * M_DIM) ? 1 : 0;

    ndft_kernel<<<B_DIM * BLOCKS_PER_B, TPB>>>(x, f_hat, out, real_only);
}